// round 1
// baseline (speedup 1.0000x reference)
#include <cuda_runtime.h>
#include <cuda_bf16.h>
#include <math.h>

// Problem constants (fixed shapes from setup_inputs)
#define B_   2
#define S_   2048
#define D_   2048
#define H_   16
#define KVH_ 4
#define DH_  128
#define M_   (B_ * S_)          // 4096
#define NQKV 3072               // 2048 q + 512 k + 512 v
#define REP_ (H_ / KVH_)        // 4

// Scratch (static device arrays; no runtime allocation allowed)
__device__ float g_qkv[M_ * NQKV];    // [m, 3072] : q(2048) | k(512) | v(512)
__device__ float g_attn[M_ * D_];     // [m, h*128+e]

// ---------------------------------------------------------------------------
// GEMM 1: C[m, n] = sum_k A[m,k] * W[n,k]   (A row-major [M,2048], W rows per n)
// 128x128x16 tiles, 8x8 micro-tile, 256 threads
// ---------------------------------------------------------------------------
__global__ __launch_bounds__(256) void gemm_qkv_kernel(
    const float* __restrict__ A,
    const float* __restrict__ WQ,
    const float* __restrict__ WK,
    const float* __restrict__ WV,
    float* __restrict__ C)
{
    __shared__ float As[16][128];
    __shared__ float Bs[16][128];
    const int K = 2048, LDA = 2048, LDC = NQKV;
    int m0 = blockIdx.y * 128;
    int n0 = blockIdx.x * 128;
    int tid = threadIdx.x;
    int tx = tid & 15, ty = tid >> 4;

    float acc[8][8];
#pragma unroll
    for (int i = 0; i < 8; i++)
#pragma unroll
        for (int j = 0; j < 8; j++) acc[i][j] = 0.f;

    for (int k0 = 0; k0 < K; k0 += 16) {
#pragma unroll
        for (int p = 0; p < 2; p++) {
            int idx = tid + p * 256;
            int r = idx >> 2;
            int c4 = (idx & 3) * 4;
            float4 v = *(const float4*)&A[(size_t)(m0 + r) * LDA + k0 + c4];
            As[c4 + 0][r] = v.x; As[c4 + 1][r] = v.y;
            As[c4 + 2][r] = v.z; As[c4 + 3][r] = v.w;
        }
#pragma unroll
        for (int p = 0; p < 2; p++) {
            int idx = tid + p * 256;
            int r = idx >> 2;
            int c4 = (idx & 3) * 4;
            int n = n0 + r;
            const float* Brow;
            if (n < 2048)       Brow = WQ + (size_t)n * 2048;
            else if (n < 2560)  Brow = WK + (size_t)(n - 2048) * 2048;
            else                Brow = WV + (size_t)(n - 2560) * 2048;
            float4 v = *(const float4*)&Brow[k0 + c4];
            Bs[c4 + 0][r] = v.x; Bs[c4 + 1][r] = v.y;
            Bs[c4 + 2][r] = v.z; Bs[c4 + 3][r] = v.w;
        }
        __syncthreads();
#pragma unroll
        for (int kk = 0; kk < 16; kk++) {
            float a[8], b[8];
            *(float4*)&a[0] = *(const float4*)&As[kk][ty * 8];
            *(float4*)&a[4] = *(const float4*)&As[kk][ty * 8 + 4];
            *(float4*)&b[0] = *(const float4*)&Bs[kk][tx * 8];
            *(float4*)&b[4] = *(const float4*)&Bs[kk][tx * 8 + 4];
#pragma unroll
            for (int i = 0; i < 8; i++)
#pragma unroll
                for (int j = 0; j < 8; j++)
                    acc[i][j] = fmaf(a[i], b[j], acc[i][j]);
        }
        __syncthreads();
    }
#pragma unroll
    for (int i = 0; i < 8; i++) {
        int row = m0 + ty * 8 + i;
        float* Cp = &C[(size_t)row * LDC + n0 + tx * 8];
        *(float4*)&Cp[0] = make_float4(acc[i][0], acc[i][1], acc[i][2], acc[i][3]);
        *(float4*)&Cp[4] = make_float4(acc[i][4], acc[i][5], acc[i][6], acc[i][7]);
    }
}

// ---------------------------------------------------------------------------
// GEMM 3: C[m, d] = sum_he A[m,he] * WO[he, d]   (B row-major [K,N])
// ---------------------------------------------------------------------------
__global__ __launch_bounds__(256) void gemm_out_kernel(
    const float* __restrict__ A,
    const float* __restrict__ Bm,
    float* __restrict__ C)
{
    __shared__ float As[16][128];
    __shared__ float Bs[16][128];
    const int K = 2048, LDA = 2048, LDB = 2048, LDC = 2048;
    int m0 = blockIdx.y * 128;
    int n0 = blockIdx.x * 128;
    int tid = threadIdx.x;
    int tx = tid & 15, ty = tid >> 4;

    float acc[8][8];
#pragma unroll
    for (int i = 0; i < 8; i++)
#pragma unroll
        for (int j = 0; j < 8; j++) acc[i][j] = 0.f;

    for (int k0 = 0; k0 < K; k0 += 16) {
#pragma unroll
        for (int p = 0; p < 2; p++) {
            int idx = tid + p * 256;
            int r = idx >> 2;
            int c4 = (idx & 3) * 4;
            float4 v = *(const float4*)&A[(size_t)(m0 + r) * LDA + k0 + c4];
            As[c4 + 0][r] = v.x; As[c4 + 1][r] = v.y;
            As[c4 + 2][r] = v.z; As[c4 + 3][r] = v.w;
        }
#pragma unroll
        for (int p = 0; p < 2; p++) {
            int idx = tid + p * 256;
            int r = idx >> 5;            // 0..15
            int c4 = (idx & 31) * 4;     // 0..124
            float4 v = *(const float4*)&Bm[(size_t)(k0 + r) * LDB + n0 + c4];
            *(float4*)&Bs[r][c4] = v;
        }
        __syncthreads();
#pragma unroll
        for (int kk = 0; kk < 16; kk++) {
            float a[8], b[8];
            *(float4*)&a[0] = *(const float4*)&As[kk][ty * 8];
            *(float4*)&a[4] = *(const float4*)&As[kk][ty * 8 + 4];
            *(float4*)&b[0] = *(const float4*)&Bs[kk][tx * 8];
            *(float4*)&b[4] = *(const float4*)&Bs[kk][tx * 8 + 4];
#pragma unroll
            for (int i = 0; i < 8; i++)
#pragma unroll
                for (int j = 0; j < 8; j++)
                    acc[i][j] = fmaf(a[i], b[j], acc[i][j]);
        }
        __syncthreads();
    }
#pragma unroll
    for (int i = 0; i < 8; i++) {
        int row = m0 + ty * 8 + i;
        float* Cp = &C[(size_t)row * LDC + n0 + tx * 8];
        *(float4*)&Cp[0] = make_float4(acc[i][0], acc[i][1], acc[i][2], acc[i][3]);
        *(float4*)&Cp[4] = make_float4(acc[i][4], acc[i][5], acc[i][6], acc[i][7]);
    }
}

// ---------------------------------------------------------------------------
// RoPE: rope q in place; rope k -> k_cache; copy v -> v_cache
// one block per (b,s), 256 threads
// ---------------------------------------------------------------------------
__global__ __launch_bounds__(256) void rope_kernel(
    float* __restrict__ qkv,
    float* __restrict__ kc,
    float* __restrict__ vc,
    const int* __restrict__ sp_ptr)
{
    const float LOG2_BASE_OVER_HALF = 13.287712379549449f / 64.0f; // log2(10000)/64
    int m = blockIdx.x;            // b*S + s
    int s = m & (S_ - 1);
    int sp = *sp_ptr;
    float pos = (float)(sp + s);
    int tid = threadIdx.x;

    // q: 16 heads x 64 pairs
    for (int p = tid; p < H_ * 64; p += 256) {
        int h = p >> 6, e = p & 63;
        float inv = exp2f(-(float)e * LOG2_BASE_OVER_HALF);
        float ang = pos * inv;
        float sn, cs;
        sincosf(ang, &sn, &cs);
        float* base = qkv + (size_t)m * NQKV + h * DH_;
        float x1 = base[e], x2 = base[e + 64];
        base[e]      = x1 * cs - x2 * sn;
        base[e + 64] = x1 * sn + x2 * cs;
    }
    // k: 4 heads x 64 pairs -> k_cache
    for (int p = tid; p < KVH_ * 64; p += 256) {
        int h = p >> 6, e = p & 63;
        float inv = exp2f(-(float)e * LOG2_BASE_OVER_HALF);
        float ang = pos * inv;
        float sn, cs;
        sincosf(ang, &sn, &cs);
        const float* base = qkv + (size_t)m * NQKV + 2048 + h * DH_;
        float x1 = base[e], x2 = base[e + 64];
        float* dst = kc + (size_t)m * (KVH_ * DH_) + h * DH_;
        dst[e]      = x1 * cs - x2 * sn;
        dst[e + 64] = x1 * sn + x2 * cs;
    }
    // v copy -> v_cache
    for (int i = tid; i < KVH_ * DH_; i += 256) {
        vc[(size_t)m * (KVH_ * DH_) + i] = qkv[(size_t)m * NQKV + 2560 + i];
    }
}

// ---------------------------------------------------------------------------
// Flash attention fp32: BM=64 q rows per block, BN=64 key tile, online softmax
// causal + ALiBi fused. Reads q from g_qkv, k/v from caches, writes g_attn.
// ---------------------------------------------------------------------------
#define ATT_SMEM_FLOATS (64*129 + 64*129 + 64*132 + 64*65 + 192)

extern "C" __global__ __launch_bounds__(256) void attn_kernel(
    const float* __restrict__ qkv,
    const float* __restrict__ kc,
    const float* __restrict__ vc,
    float* __restrict__ attn,
    const int* __restrict__ sp_ptr)
{
    extern __shared__ float smem[];
    float* Qs = smem;                 // [64][129]
    float* Ks = Qs + 64 * 129;        // [64][129]
    float* Vs = Ks + 64 * 129;        // [64][132]
    float* Ps = Vs + 64 * 132;        // [64][65]
    float* sm_m = Ps + 64 * 65;       // [64]
    float* sm_l = sm_m + 64;          // [64]
    float* sm_c = sm_l + 64;          // [64]

    int bh = blockIdx.y;
    int b = bh >> 4;
    int h = bh & 15;
    int kvh = h >> 2;                 // rep = 4
    int q0 = blockIdx.x * 64;
    int sp = *sp_ptr;
    float slope = exp2f(-0.5f * (float)(h + 1));
    const float scale = 0.08838834764831845f;  // 1/sqrt(128)

    int tid = threadIdx.x;
    int tx = tid & 15, ty = tid >> 4;          // phase A mapping (4x4)
    int ctx = tid & 15, cty = tid >> 4;        // phase C mapping (4 rows x 8 cols)

    // load + scale Q tile (64 x 128)
#pragma unroll
    for (int p = 0; p < 8; p++) {
        int idx = tid + p * 256;
        int r = idx >> 5;
        int c = (idx & 31) * 4;
        float4 v = *(const float4*)&qkv[(size_t)(b * S_ + q0 + r) * NQKV + h * DH_ + c];
        float* q = &Qs[r * 129 + c];
        q[0] = v.x * scale; q[1] = v.y * scale; q[2] = v.z * scale; q[3] = v.w * scale;
    }
    if (tid < 64) { sm_m[tid] = -1e30f; sm_l[tid] = 0.f; }

    float Oacc[4][8];
#pragma unroll
    for (int i = 0; i < 4; i++)
#pragma unroll
        for (int j = 0; j < 8; j++) Oacc[i][j] = 0.f;

    int kt_end = (sp + q0 + 63) >> 6;
    if (kt_end > (S_ / 64 - 1)) kt_end = S_ / 64 - 1;
    __syncthreads();

    for (int kt = 0; kt <= kt_end; kt++) {
        int k0 = kt * 64;
        // load K and V tiles
#pragma unroll
        for (int p = 0; p < 8; p++) {
            int idx = tid + p * 256;
            int r = idx >> 5;
            int c = (idx & 31) * 4;
            size_t goff = ((size_t)(b * S_ + k0 + r) * KVH_ + kvh) * DH_ + c;
            float4 kv = *(const float4*)&kc[goff];
            float* kd = &Ks[r * 129 + c];
            kd[0] = kv.x; kd[1] = kv.y; kd[2] = kv.z; kd[3] = kv.w;
            float4 vv = *(const float4*)&vc[goff];
            float* vd = &Vs[r * 132 + c];
            vd[0] = vv.x; vd[1] = vv.y; vd[2] = vv.z; vd[3] = vv.w;
        }
        __syncthreads();

        // phase A: S = Q K^T (scaled), 4x4 per thread
        float sacc[4][4];
#pragma unroll
        for (int i = 0; i < 4; i++)
#pragma unroll
            for (int j = 0; j < 4; j++) sacc[i][j] = 0.f;

#pragma unroll 4
        for (int kk = 0; kk < 128; kk++) {
            float a[4], bq[4];
#pragma unroll
            for (int i = 0; i < 4; i++) a[i] = Qs[(ty * 4 + i) * 129 + kk];
#pragma unroll
            for (int j = 0; j < 4; j++) bq[j] = Ks[(tx * 4 + j) * 129 + kk];
#pragma unroll
            for (int i = 0; i < 4; i++)
#pragma unroll
                for (int j = 0; j < 4; j++)
                    sacc[i][j] = fmaf(a[i], bq[j], sacc[i][j]);
        }

        // mask + ALiBi bias, store P
#pragma unroll
        for (int i = 0; i < 4; i++) {
            int qi = q0 + ty * 4 + i;
            int qpos = sp + qi;
#pragma unroll
            for (int j = 0; j < 4; j++) {
                int kj = k0 + tx * 4 + j;
                float v;
                if (kj <= qpos)
                    v = sacc[i][j] - slope * (float)(qpos - kj);
                else
                    v = -1e30f;
                Ps[(ty * 4 + i) * 65 + tx * 4 + j] = v;
            }
        }
        __syncthreads();

        // online softmax row update (one thread per row)
        if (tid < 64) {
            float mo = sm_m[tid];
            float mx = mo;
            float* pr = Ps + tid * 65;
#pragma unroll 8
            for (int j = 0; j < 64; j++) mx = fmaxf(mx, pr[j]);
            float corr = __expf(mo - mx);
            float ls = 0.f;
#pragma unroll 8
            for (int j = 0; j < 64; j++) {
                float s = pr[j];
                float e = (s > -1e29f) ? __expf(s - mx) : 0.f;
                pr[j] = e;
                ls += e;
            }
            sm_m[tid] = mx;
            sm_l[tid] = sm_l[tid] * corr + ls;
            sm_c[tid] = corr;
        }
        __syncthreads();

        // rescale accumulators
        float cr[4];
#pragma unroll
        for (int i = 0; i < 4; i++) cr[i] = sm_c[cty * 4 + i];
#pragma unroll
        for (int i = 0; i < 4; i++)
#pragma unroll
            for (int j = 0; j < 8; j++) Oacc[i][j] *= cr[i];

        // phase C: O += P * V  (rows cty*4+i, cols ctx*8..+7)
#pragma unroll 2
        for (int j = 0; j < 64; j++) {
            float pv[4];
#pragma unroll
            for (int i = 0; i < 4; i++) pv[i] = Ps[(cty * 4 + i) * 65 + j];
            float vv[8];
            *(float4*)&vv[0] = *(const float4*)&Vs[j * 132 + ctx * 8];
            *(float4*)&vv[4] = *(const float4*)&Vs[j * 132 + ctx * 8 + 4];
#pragma unroll
            for (int i = 0; i < 4; i++)
#pragma unroll
                for (int jc = 0; jc < 8; jc++)
                    Oacc[i][jc] = fmaf(pv[i], vv[jc], Oacc[i][jc]);
        }
        __syncthreads();
    }

    // normalize + write out
#pragma unroll
    for (int i = 0; i < 4; i++) {
        int r = cty * 4 + i;
        float inv_l = 1.0f / sm_l[r];
        float* dst = &attn[(size_t)(b * S_ + q0 + r) * D_ + h * DH_ + ctx * 8];
        float4 o0 = make_float4(Oacc[i][0] * inv_l, Oacc[i][1] * inv_l,
                                Oacc[i][2] * inv_l, Oacc[i][3] * inv_l);
        float4 o1 = make_float4(Oacc[i][4] * inv_l, Oacc[i][5] * inv_l,
                                Oacc[i][6] * inv_l, Oacc[i][7] * inv_l);
        *(float4*)&dst[0] = o0;
        *(float4*)&dst[4] = o1;
    }
}

// ---------------------------------------------------------------------------
extern "C" void kernel_launch(void* const* d_in, const int* in_sizes, int n_in,
                              void* d_out, int out_size)
{
    const float* residual = (const float*)d_in[0];
    const float* W_Q = (const float*)d_in[1];
    const float* W_K = (const float*)d_in[2];
    const float* W_V = (const float*)d_in[3];
    const float* W_O = (const float*)d_in[4];
    const int* sp = (const int*)d_in[5];

    float* out = (float*)d_out;                         // [B,S,D]
    float* k_cache = out + (size_t)B_ * S_ * D_;        // [B,S,KVH,Dh]
    float* v_cache = k_cache + (size_t)B_ * S_ * KVH_ * DH_;

    float* qkv_ptr = nullptr;
    float* attn_ptr = nullptr;
    cudaGetSymbolAddress((void**)&qkv_ptr, g_qkv);
    cudaGetSymbolAddress((void**)&attn_ptr, g_attn);

    // 1) fused QKV projection
    gemm_qkv_kernel<<<dim3(NQKV / 128, M_ / 128), 256>>>(
        residual, W_Q, W_K, W_V, qkv_ptr);

    // 2) RoPE (q in place; k -> k_cache; v -> v_cache)
    rope_kernel<<<M_, 256>>>(qkv_ptr, k_cache, v_cache, sp);

    // 3) attention
    int smem_bytes = ATT_SMEM_FLOATS * 4;
    cudaFuncSetAttribute(attn_kernel, cudaFuncAttributeMaxDynamicSharedMemorySize,
                         smem_bytes);
    attn_kernel<<<dim3(S_ / 64, B_ * H_), 256, smem_bytes>>>(
        qkv_ptr, k_cache, v_cache, attn_ptr, sp);

    // 4) output projection
    gemm_out_kernel<<<dim3(D_ / 128, M_ / 128), 256>>>(attn_ptr, W_O, out);
}

// round 3
// speedup vs baseline: 1.5407x; 1.5407x over previous
#include <cuda_runtime.h>
#include <cuda_bf16.h>
#include <math.h>
#include <stdint.h>

// Problem constants (fixed shapes from setup_inputs)
#define B_   2
#define S_   2048
#define D_   2048
#define H_   16
#define KVH_ 4
#define DH_  128
#define M_   (B_ * S_)          // 4096
#define NQKV 3072               // 2048 q + 512 k + 512 v

// Scratch (static device arrays; no runtime allocation allowed)
__device__ float g_qkv[M_ * NQKV];    // [m, 3072] : q(2048) | k(512) | v(512)
__device__ float g_attn[M_ * D_];     // [m, h*128+e]
__device__ __nv_bfloat16 g_Ahi[M_ * D_];
__device__ __nv_bfloat16 g_Alo[M_ * D_];
__device__ __nv_bfloat16 g_Whi[NQKV * D_];
__device__ __nv_bfloat16 g_Wlo[NQKV * D_];
__device__ __nv_bfloat16 g_WOhi[D_ * D_];   // transposed: [d][he]
__device__ __nv_bfloat16 g_WOlo[D_ * D_];
__device__ __nv_bfloat16 g_Phi[M_ * D_];
__device__ __nv_bfloat16 g_Plo[M_ * D_];

// ---------------------------------------------------------------------------
// helpers
// ---------------------------------------------------------------------------
__device__ __forceinline__ uint32_t smem_u32(const void* p) {
    uint32_t a;
    asm("{ .reg .u64 t; cvta.to.shared.u64 t, %1; cvt.u32.u64 %0, t; }"
        : "=r"(a) : "l"(p));
    return a;
}

__device__ __forceinline__ void cp16(uint32_t dst, const void* src) {
    asm volatile("cp.async.cg.shared.global [%0], [%1], 16;"
                 :: "r"(dst), "l"(src));
}

__device__ __forceinline__ void ldm_x4(uint32_t* r, uint32_t addr) {
    asm volatile("ldmatrix.sync.aligned.m8n8.x4.shared.b16 {%0,%1,%2,%3}, [%4];"
                 : "=r"(r[0]), "=r"(r[1]), "=r"(r[2]), "=r"(r[3]) : "r"(addr));
}

__device__ __forceinline__ void mma_bf16(float* c, const uint32_t* a,
                                         uint32_t b0, uint32_t b1) {
    asm volatile(
        "mma.sync.aligned.m16n8k16.row.col.f32.bf16.bf16.f32 "
        "{%0,%1,%2,%3}, {%4,%5,%6,%7}, {%8,%9}, {%0,%1,%2,%3};"
        : "+f"(c[0]), "+f"(c[1]), "+f"(c[2]), "+f"(c[3])
        : "r"(a[0]), "r"(a[1]), "r"(a[2]), "r"(a[3]), "r"(b0), "r"(b1));
}

// swizzled byte offset for a 16B segment (row r, seg s) in a [128][32]bf16 block
__device__ __forceinline__ uint32_t swz_off(int r, int s) {
    return (uint32_t)(r * 64 + ((s ^ ((r >> 1) & 3)) * 16));
}

// ---------------------------------------------------------------------------
// HMMA GEMM: C[m,n] = sum_k A[m,k]*B[n,k] in fp32 via split-bf16 (hh+hl+lh).
// CTA tile 128x128, K=2048, K-chunk 32, 8 warps (4m x 2n), warp tile 32x64.
// Double-buffered cp.async smem: per buffer 4 blocks [128][32]bf16 (Ah,Al,Bh,Bl)
// ---------------------------------------------------------------------------
#define GEMM_SMEM (2 * 4 * 8192)

__global__ __launch_bounds__(256) void hmma_gemm(
    const __nv_bfloat16* __restrict__ Ah, const __nv_bfloat16* __restrict__ Al,
    const __nv_bfloat16* __restrict__ Bh, const __nv_bfloat16* __restrict__ Bl,
    float* __restrict__ C, int ldc)
{
    extern __shared__ char smem[];
    uint32_t sb = smem_u32(smem);

    int tid = threadIdx.x;
    int lane = tid & 31;
    int warp = tid >> 5;
    int warp_m = warp & 3;       // 0..3
    int warp_n = warp >> 2;      // 0..1
    int m0 = blockIdx.y * 128;
    int n0 = blockIdx.x * 128;

    // ldmatrix per-lane row/seg decomposition
    int q = lane >> 3;           // 0..3 (which 8x8 matrix)
    int lrow = lane & 7;         // row within 8x8
    int arow_l = (q & 1) * 8 + lrow;   // local row within 16
    int ksel = q >> 1;           // 0/1: which k8 half of k16

    float acc[2][8][4];
#pragma unroll
    for (int i = 0; i < 2; i++)
#pragma unroll
        for (int j = 0; j < 8; j++)
#pragma unroll
            for (int k = 0; k < 4; k++) acc[i][j][k] = 0.f;

    auto load_chunk = [&](int c) {
        int k0 = c * 32;
        uint32_t buf = sb + (uint32_t)(c & 1) * 32768u;
#pragma unroll
        for (int t = 0; t < 8; t++) {
            int g = tid + t * 256;          // 0..2047
            int mat = g >> 9;               // 0:Ah 1:Al 2:Bh 3:Bl
            int inner = g & 511;
            int r = inner >> 2;             // 0..127
            int s = inner & 3;              // 0..3
            const __nv_bfloat16* base =
                (mat == 0) ? Ah : (mat == 1) ? Al : (mat == 2) ? Bh : Bl;
            int row = ((mat < 2) ? m0 : n0) + r;
            const void* src = base + (size_t)row * 2048 + k0 + s * 8;
            cp16(buf + (uint32_t)mat * 8192u + swz_off(r, s), src);
        }
        asm volatile("cp.async.commit_group;" ::: "memory");
    };

    load_chunk(0);

    for (int c = 0; c < 64; c++) {
        if (c + 1 < 64) load_chunk(c + 1);
        if (c + 1 < 64) asm volatile("cp.async.wait_group 1;" ::: "memory");
        else            asm volatile("cp.async.wait_group 0;" ::: "memory");
        __syncthreads();

        uint32_t buf = sb + (uint32_t)(c & 1) * 32768u;
        uint32_t bAh = buf, bAl = buf + 8192, bBh = buf + 16384, bBl = buf + 24576;

#pragma unroll
        for (int ks = 0; ks < 2; ks++) {
            int s = ks * 2 + ksel;
            // A fragments: 2 m16 tiles, hi and lo
            uint32_t ah[2][4], al[2][4];
#pragma unroll
            for (int mi = 0; mi < 2; mi++) {
                int r = warp_m * 32 + mi * 16 + arow_l;
                ldm_x4(ah[mi], bAh + swz_off(r, s));
                ldm_x4(al[mi], bAl + swz_off(r, s));
            }
            // B fragments: 4 ldmatrix.x4 each cover n16 -> 8 n8 frags
            uint32_t bh[8][2], bl[8][2];
#pragma unroll
            for (int j = 0; j < 4; j++) {
                int r = warp_n * 64 + j * 16 + arow_l;
                uint32_t t4[4];
                ldm_x4(t4, bBh + swz_off(r, s));
                bh[j * 2 + 0][0] = t4[0]; bh[j * 2 + 0][1] = t4[2];
                bh[j * 2 + 1][0] = t4[1]; bh[j * 2 + 1][1] = t4[3];
                ldm_x4(t4, bBl + swz_off(r, s));
                bl[j * 2 + 0][0] = t4[0]; bl[j * 2 + 0][1] = t4[2];
                bl[j * 2 + 1][0] = t4[1]; bl[j * 2 + 1][1] = t4[3];
            }
#pragma unroll
            for (int mi = 0; mi < 2; mi++) {
#pragma unroll
                for (int nj = 0; nj < 8; nj++) {
                    mma_bf16(acc[mi][nj], ah[mi], bh[nj][0], bh[nj][1]);
                    mma_bf16(acc[mi][nj], ah[mi], bl[nj][0], bl[nj][1]);
                    mma_bf16(acc[mi][nj], al[mi], bh[nj][0], bh[nj][1]);
                }
            }
        }
        __syncthreads();
    }

    // epilogue: c-frag lane mapping: rows lane>>2 (+8), cols 2*(lane&3)
    int rr = lane >> 2;
    int cc = (lane & 3) * 2;
#pragma unroll
    for (int mi = 0; mi < 2; mi++) {
        int r1 = m0 + warp_m * 32 + mi * 16 + rr;
#pragma unroll
        for (int nj = 0; nj < 8; nj++) {
            int col = n0 + warp_n * 64 + nj * 8 + cc;
            float2 v0 = make_float2(acc[mi][nj][0], acc[mi][nj][1]);
            float2 v1 = make_float2(acc[mi][nj][2], acc[mi][nj][3]);
            *(float2*)&C[(size_t)r1 * ldc + col] = v0;
            *(float2*)&C[(size_t)(r1 + 8) * ldc + col] = v1;
        }
    }
}

// ---------------------------------------------------------------------------
// Elementwise fp32 -> (bf16 hi, bf16 lo) split
// ---------------------------------------------------------------------------
__global__ __launch_bounds__(256) void split_kernel(
    const float* __restrict__ src, __nv_bfloat16* __restrict__ hi,
    __nv_bfloat16* __restrict__ lo, int n4)
{
    int i = blockIdx.x * 256 + threadIdx.x;
    if (i >= n4) return;
    float4 v = ((const float4*)src)[i];
    __nv_bfloat16 h0 = __float2bfloat16(v.x);
    __nv_bfloat16 h1 = __float2bfloat16(v.y);
    __nv_bfloat16 h2 = __float2bfloat16(v.z);
    __nv_bfloat16 h3 = __float2bfloat16(v.w);
    __nv_bfloat16 l0 = __float2bfloat16(v.x - __bfloat162float(h0));
    __nv_bfloat16 l1 = __float2bfloat16(v.y - __bfloat162float(h1));
    __nv_bfloat16 l2 = __float2bfloat16(v.z - __bfloat162float(h2));
    __nv_bfloat16 l3 = __float2bfloat16(v.w - __bfloat162float(h3));
    ushort4 hv = make_ushort4(__bfloat16_as_ushort(h0), __bfloat16_as_ushort(h1),
                              __bfloat16_as_ushort(h2), __bfloat16_as_ushort(h3));
    ushort4 lv = make_ushort4(__bfloat16_as_ushort(l0), __bfloat16_as_ushort(l1),
                              __bfloat16_as_ushort(l2), __bfloat16_as_ushort(l3));
    ((ushort4*)hi)[i] = hv;
    ((ushort4*)lo)[i] = lv;
}

// ---------------------------------------------------------------------------
// Transpose + split W_O: in [he=2048][d=2048] -> out [d][he] hi/lo bf16
// ---------------------------------------------------------------------------
__global__ __launch_bounds__(256) void transpose_split_wo(
    const float* __restrict__ W, __nv_bfloat16* __restrict__ Th,
    __nv_bfloat16* __restrict__ Tl)
{
    __shared__ float t[32][33];
    int bx = blockIdx.x * 32;   // d tile
    int by = blockIdx.y * 32;   // he tile
    int x = threadIdx.x & 31;
    int y0 = threadIdx.x >> 5;  // 0..7
#pragma unroll
    for (int i = 0; i < 32; i += 8)
        t[y0 + i][x] = W[(size_t)(by + y0 + i) * 2048 + bx + x];
    __syncthreads();
#pragma unroll
    for (int i = 0; i < 32; i += 8) {
        float v = t[x][y0 + i];
        __nv_bfloat16 h = __float2bfloat16(v);
        __nv_bfloat16 l = __float2bfloat16(v - __bfloat162float(h));
        size_t o = (size_t)(bx + y0 + i) * 2048 + by + x;
        Th[o] = h;
        Tl[o] = l;
    }
}

// ---------------------------------------------------------------------------
// RoPE: rope q in place; rope k -> k_cache; copy v -> v_cache
// ---------------------------------------------------------------------------
__global__ __launch_bounds__(256) void rope_kernel(
    float* __restrict__ qkv,
    float* __restrict__ kc,
    float* __restrict__ vc,
    const int* __restrict__ sp_ptr)
{
    const float LOG2_BASE_OVER_HALF = 13.287712379549449f / 64.0f;
    int m = blockIdx.x;
    int s = m & (S_ - 1);
    int sp = *sp_ptr;
    float pos = (float)(sp + s);
    int tid = threadIdx.x;

    for (int p = tid; p < H_ * 64; p += 256) {
        int h = p >> 6, e = p & 63;
        float inv = exp2f(-(float)e * LOG2_BASE_OVER_HALF);
        float ang = pos * inv;
        float sn, cs;
        sincosf(ang, &sn, &cs);
        float* base = qkv + (size_t)m * NQKV + h * DH_;
        float x1 = base[e], x2 = base[e + 64];
        base[e]      = x1 * cs - x2 * sn;
        base[e + 64] = x1 * sn + x2 * cs;
    }
    for (int p = tid; p < KVH_ * 64; p += 256) {
        int h = p >> 6, e = p & 63;
        float inv = exp2f(-(float)e * LOG2_BASE_OVER_HALF);
        float ang = pos * inv;
        float sn, cs;
        sincosf(ang, &sn, &cs);
        const float* base = qkv + (size_t)m * NQKV + 2048 + h * DH_;
        float x1 = base[e], x2 = base[e + 64];
        float* dst = kc + (size_t)m * (KVH_ * DH_) + h * DH_;
        dst[e]      = x1 * cs - x2 * sn;
        dst[e + 64] = x1 * sn + x2 * cs;
    }
    for (int i = tid; i < KVH_ * DH_; i += 256) {
        vc[(size_t)m * (KVH_ * DH_) + i] = qkv[(size_t)m * NQKV + 2560 + i];
    }
}

// ---------------------------------------------------------------------------
// Flash attention fp32 (unchanged): BM=64, BN=64, online softmax
// ---------------------------------------------------------------------------
#define ATT_SMEM_FLOATS (64*129 + 64*129 + 64*132 + 64*65 + 192)

extern "C" __global__ __launch_bounds__(256) void attn_kernel(
    const float* __restrict__ qkv,
    const float* __restrict__ kc,
    const float* __restrict__ vc,
    float* __restrict__ attn,
    const int* __restrict__ sp_ptr)
{
    extern __shared__ float smemf[];
    float* Qs = smemf;
    float* Ks = Qs + 64 * 129;
    float* Vs = Ks + 64 * 129;
    float* Ps = Vs + 64 * 132;
    float* sm_m = Ps + 64 * 65;
    float* sm_l = sm_m + 64;
    float* sm_c = sm_l + 64;

    int bh = blockIdx.y;
    int b = bh >> 4;
    int h = bh & 15;
    int kvh = h >> 2;
    int q0 = blockIdx.x * 64;
    int sp = *sp_ptr;
    float slope = exp2f(-0.5f * (float)(h + 1));
    const float scale = 0.08838834764831845f;

    int tid = threadIdx.x;
    int tx = tid & 15, ty = tid >> 4;
    int ctx = tid & 15, cty = tid >> 4;

#pragma unroll
    for (int p = 0; p < 8; p++) {
        int idx = tid + p * 256;
        int r = idx >> 5;
        int c = (idx & 31) * 4;
        float4 v = *(const float4*)&qkv[(size_t)(b * S_ + q0 + r) * NQKV + h * DH_ + c];
        float* q = &Qs[r * 129 + c];
        q[0] = v.x * scale; q[1] = v.y * scale; q[2] = v.z * scale; q[3] = v.w * scale;
    }
    if (tid < 64) { sm_m[tid] = -1e30f; sm_l[tid] = 0.f; }

    float Oacc[4][8];
#pragma unroll
    for (int i = 0; i < 4; i++)
#pragma unroll
        for (int j = 0; j < 8; j++) Oacc[i][j] = 0.f;

    int kt_end = (sp + q0 + 63) >> 6;
    if (kt_end > (S_ / 64 - 1)) kt_end = S_ / 64 - 1;
    __syncthreads();

    for (int kt = 0; kt <= kt_end; kt++) {
        int k0 = kt * 64;
#pragma unroll
        for (int p = 0; p < 8; p++) {
            int idx = tid + p * 256;
            int r = idx >> 5;
            int c = (idx & 31) * 4;
            size_t goff = ((size_t)(b * S_ + k0 + r) * KVH_ + kvh) * DH_ + c;
            float4 kv = *(const float4*)&kc[goff];
            float* kd = &Ks[r * 129 + c];
            kd[0] = kv.x; kd[1] = kv.y; kd[2] = kv.z; kd[3] = kv.w;
            float4 vv = *(const float4*)&vc[goff];
            float* vd = &Vs[r * 132 + c];
            vd[0] = vv.x; vd[1] = vv.y; vd[2] = vv.z; vd[3] = vv.w;
        }
        __syncthreads();

        float sacc[4][4];
#pragma unroll
        for (int i = 0; i < 4; i++)
#pragma unroll
            for (int j = 0; j < 4; j++) sacc[i][j] = 0.f;

#pragma unroll 4
        for (int kk = 0; kk < 128; kk++) {
            float a[4], bq[4];
#pragma unroll
            for (int i = 0; i < 4; i++) a[i] = Qs[(ty * 4 + i) * 129 + kk];
#pragma unroll
            for (int j = 0; j < 4; j++) bq[j] = Ks[(tx * 4 + j) * 129 + kk];
#pragma unroll
            for (int i = 0; i < 4; i++)
#pragma unroll
                for (int j = 0; j < 4; j++)
                    sacc[i][j] = fmaf(a[i], bq[j], sacc[i][j]);
        }

#pragma unroll
        for (int i = 0; i < 4; i++) {
            int qi = q0 + ty * 4 + i;
            int qpos = sp + qi;
#pragma unroll
            for (int j = 0; j < 4; j++) {
                int kj = k0 + tx * 4 + j;
                float v;
                if (kj <= qpos)
                    v = sacc[i][j] - slope * (float)(qpos - kj);
                else
                    v = -1e30f;
                Ps[(ty * 4 + i) * 65 + tx * 4 + j] = v;
            }
        }
        __syncthreads();

        if (tid < 64) {
            float mo = sm_m[tid];
            float mx = mo;
            float* pr = Ps + tid * 65;
#pragma unroll 8
            for (int j = 0; j < 64; j++) mx = fmaxf(mx, pr[j]);
            float corr = __expf(mo - mx);
            float ls = 0.f;
#pragma unroll 8
            for (int j = 0; j < 64; j++) {
                float s = pr[j];
                float e = (s > -1e29f) ? __expf(s - mx) : 0.f;
                pr[j] = e;
                ls += e;
            }
            sm_m[tid] = mx;
            sm_l[tid] = sm_l[tid] * corr + ls;
            sm_c[tid] = corr;
        }
        __syncthreads();

        float cr[4];
#pragma unroll
        for (int i = 0; i < 4; i++) cr[i] = sm_c[cty * 4 + i];
#pragma unroll
        for (int i = 0; i < 4; i++)
#pragma unroll
            for (int j = 0; j < 8; j++) Oacc[i][j] *= cr[i];

#pragma unroll 2
        for (int j = 0; j < 64; j++) {
            float pv[4];
#pragma unroll
            for (int i = 0; i < 4; i++) pv[i] = Ps[(cty * 4 + i) * 65 + j];
            float vv[8];
            *(float4*)&vv[0] = *(const float4*)&Vs[j * 132 + ctx * 8];
            *(float4*)&vv[4] = *(const float4*)&Vs[j * 132 + ctx * 8 + 4];
#pragma unroll
            for (int i = 0; i < 4; i++)
#pragma unroll
                for (int jc = 0; jc < 8; jc++)
                    Oacc[i][jc] = fmaf(pv[i], vv[jc], Oacc[i][jc]);
        }
        __syncthreads();
    }

#pragma unroll
    for (int i = 0; i < 4; i++) {
        int r = cty * 4 + i;
        float inv_l = 1.0f / sm_l[r];
        float* dst = &attn[(size_t)(b * S_ + q0 + r) * D_ + h * DH_ + ctx * 8];
        float4 o0 = make_float4(Oacc[i][0] * inv_l, Oacc[i][1] * inv_l,
                                Oacc[i][2] * inv_l, Oacc[i][3] * inv_l);
        float4 o1 = make_float4(Oacc[i][4] * inv_l, Oacc[i][5] * inv_l,
                                Oacc[i][6] * inv_l, Oacc[i][7] * inv_l);
        *(float4*)&dst[0] = o0;
        *(float4*)&dst[4] = o1;
    }
}

// ---------------------------------------------------------------------------
extern "C" void kernel_launch(void* const* d_in, const int* in_sizes, int n_in,
                              void* d_out, int out_size)
{
    const float* residual = (const float*)d_in[0];
    const float* W_Q = (const float*)d_in[1];
    const float* W_K = (const float*)d_in[2];
    const float* W_V = (const float*)d_in[3];
    const float* W_O = (const float*)d_in[4];
    const int* sp = (const int*)d_in[5];

    float* out = (float*)d_out;
    float* k_cache = out + (size_t)B_ * S_ * D_;
    float* v_cache = k_cache + (size_t)B_ * S_ * KVH_ * DH_;

    float *qkv_ptr, *attn_ptr;
    __nv_bfloat16 *Ahi, *Alo, *Whi, *Wlo, *WOhi, *WOlo, *Phi, *Plo;
    cudaGetSymbolAddress((void**)&qkv_ptr, g_qkv);
    cudaGetSymbolAddress((void**)&attn_ptr, g_attn);
    cudaGetSymbolAddress((void**)&Ahi, g_Ahi);
    cudaGetSymbolAddress((void**)&Alo, g_Alo);
    cudaGetSymbolAddress((void**)&Whi, g_Whi);
    cudaGetSymbolAddress((void**)&Wlo, g_Wlo);
    cudaGetSymbolAddress((void**)&WOhi, g_WOhi);
    cudaGetSymbolAddress((void**)&WOlo, g_WOlo);
    cudaGetSymbolAddress((void**)&Phi, g_Phi);
    cudaGetSymbolAddress((void**)&Plo, g_Plo);

    cudaFuncSetAttribute(hmma_gemm, cudaFuncAttributeMaxDynamicSharedMemorySize,
                         GEMM_SMEM);
    cudaFuncSetAttribute(attn_kernel, cudaFuncAttributeMaxDynamicSharedMemorySize,
                         ATT_SMEM_FLOATS * 4);

    // 0) splits: residual, W_Q/K/V (concatenated rows), W_O transposed
    split_kernel<<<(M_ * D_ / 4 + 255) / 256, 256>>>(residual, Ahi, Alo, M_ * D_ / 4);
    split_kernel<<<(2048 * 2048 / 4 + 255) / 256, 256>>>(W_Q, Whi, Wlo, 2048 * 2048 / 4);
    split_kernel<<<(512 * 2048 / 4 + 255) / 256, 256>>>(
        W_K, Whi + (size_t)2048 * 2048, Wlo + (size_t)2048 * 2048, 512 * 2048 / 4);
    split_kernel<<<(512 * 2048 / 4 + 255) / 256, 256>>>(
        W_V, Whi + (size_t)2560 * 2048, Wlo + (size_t)2560 * 2048, 512 * 2048 / 4);
    transpose_split_wo<<<dim3(64, 64), 256>>>(W_O, WOhi, WOlo);

    // 1) fused QKV projection (HMMA split-bf16)
    hmma_gemm<<<dim3(NQKV / 128, M_ / 128), 256, GEMM_SMEM>>>(
        Ahi, Alo, Whi, Wlo, qkv_ptr, NQKV);

    // 2) RoPE
    rope_kernel<<<M_, 256>>>(qkv_ptr, k_cache, v_cache, sp);

    // 3) attention
    attn_kernel<<<dim3(S_ / 64, B_ * H_), 256, ATT_SMEM_FLOATS * 4>>>(
        qkv_ptr, k_cache, v_cache, attn_ptr, sp);

    // 4) split attention output, then output projection (HMMA split-bf16)
    split_kernel<<<(M_ * D_ / 4 + 255) / 256, 256>>>(attn_ptr, Phi, Plo, M_ * D_ / 4);
    hmma_gemm<<<dim3(D_ / 128, M_ / 128), 256, GEMM_SMEM>>>(
        Phi, Plo, WOhi, WOlo, out, D_);
}

// round 4
// speedup vs baseline: 3.3316x; 2.1623x over previous
#include <cuda_runtime.h>
#include <cuda_bf16.h>
#include <math.h>
#include <stdint.h>

// Problem constants (fixed shapes from setup_inputs)
#define B_   2
#define S_   2048
#define D_   2048
#define H_   16
#define KVH_ 4
#define DH_  128
#define M_   (B_ * S_)          // 4096
#define NQKV 3072               // 2048 q + 512 k + 512 v

// Scratch (static device arrays; no runtime allocation allowed)
__device__ float g_qkv[M_ * NQKV];    // [m, 3072] : q(2048) | k(512) | v(512)
__device__ __nv_bfloat16 g_Ahi[M_ * D_];   // residual split; reused as Q hi after rope
__device__ __nv_bfloat16 g_Alo[M_ * D_];
__device__ __nv_bfloat16 g_Whi[NQKV * D_];
__device__ __nv_bfloat16 g_Wlo[NQKV * D_];
__device__ __nv_bfloat16 g_WOhi[D_ * D_];   // transposed: [d][he]
__device__ __nv_bfloat16 g_WOlo[D_ * D_];
__device__ __nv_bfloat16 g_Phi[M_ * D_];    // attention output split
__device__ __nv_bfloat16 g_Plo[M_ * D_];
__device__ __nv_bfloat16 g_Khi[M_ * 512];
__device__ __nv_bfloat16 g_Klo[M_ * 512];
__device__ __nv_bfloat16 g_Vhi[M_ * 512];
__device__ __nv_bfloat16 g_Vlo[M_ * 512];

// ---------------------------------------------------------------------------
// helpers
// ---------------------------------------------------------------------------
__device__ __forceinline__ uint32_t smem_u32(const void* p) {
    uint32_t a;
    asm("{ .reg .u64 t; cvta.to.shared.u64 t, %1; cvt.u32.u64 %0, t; }"
        : "=r"(a) : "l"(p));
    return a;
}

__device__ __forceinline__ void cp16(uint32_t dst, const void* src) {
    asm volatile("cp.async.cg.shared.global [%0], [%1], 16;"
                 :: "r"(dst), "l"(src));
}

__device__ __forceinline__ void ldm_x4(uint32_t* r, uint32_t addr) {
    asm volatile("ldmatrix.sync.aligned.m8n8.x4.shared.b16 {%0,%1,%2,%3}, [%4];"
                 : "=r"(r[0]), "=r"(r[1]), "=r"(r[2]), "=r"(r[3]) : "r"(addr));
}

__device__ __forceinline__ void ldm_x4_t(uint32_t* r, uint32_t addr) {
    asm volatile("ldmatrix.sync.aligned.m8n8.x4.trans.shared.b16 {%0,%1,%2,%3}, [%4];"
                 : "=r"(r[0]), "=r"(r[1]), "=r"(r[2]), "=r"(r[3]) : "r"(addr));
}

__device__ __forceinline__ void mma_bf16(float* c, const uint32_t* a,
                                         uint32_t b0, uint32_t b1) {
    asm volatile(
        "mma.sync.aligned.m16n8k16.row.col.f32.bf16.bf16.f32 "
        "{%0,%1,%2,%3}, {%4,%5,%6,%7}, {%8,%9}, {%0,%1,%2,%3};"
        : "+f"(c[0]), "+f"(c[1]), "+f"(c[2]), "+f"(c[3])
        : "r"(a[0]), "r"(a[1]), "r"(a[2]), "r"(a[3]), "r"(b0), "r"(b1));
}

// swizzled byte offset for a 16B segment (row r, seg s) in a [128][32]bf16 block
__device__ __forceinline__ uint32_t swz_off(int r, int s) {
    return (uint32_t)(r * 64 + ((s ^ ((r >> 1) & 3)) * 16));
}

// swizzled byte offset for [64 rows][128 bf16] tiles (256B rows, 16 segs)
__device__ __forceinline__ uint32_t aswz(int r, int sg) {
    return (uint32_t)(r * 256 + ((sg ^ (r & 7)) * 16));
}

__device__ __forceinline__ uint32_t pack_hi2(float x0, float x1, float& r0, float& r1) {
    __nv_bfloat16 h0 = __float2bfloat16(x0);
    __nv_bfloat16 h1 = __float2bfloat16(x1);
    r0 = x0 - __bfloat162float(h0);
    r1 = x1 - __bfloat162float(h1);
    __nv_bfloat162 p = __halves2bfloat162(h0, h1);   // x = h0 (low), y = h1 (high)
    return *(uint32_t*)&p;
}

__device__ __forceinline__ uint32_t pack_bf2(float x0, float x1) {
    __nv_bfloat162 p = __floats2bfloat162_rn(x0, x1);
    return *(uint32_t*)&p;
}

// ---------------------------------------------------------------------------
// HMMA GEMM: C[m,n] = sum_k A[m,k]*B[n,k] in fp32 via split-bf16 (hh+hl+lh).
// CTA tile 128x128, K=2048, K-chunk 32, 8 warps (4m x 2n), warp tile 32x64.
// ---------------------------------------------------------------------------
#define GEMM_SMEM (2 * 4 * 8192)

__global__ __launch_bounds__(256) void hmma_gemm(
    const __nv_bfloat16* __restrict__ Ah, const __nv_bfloat16* __restrict__ Al,
    const __nv_bfloat16* __restrict__ Bh, const __nv_bfloat16* __restrict__ Bl,
    float* __restrict__ C, int ldc)
{
    extern __shared__ char smem[];
    uint32_t sb = smem_u32(smem);

    int tid = threadIdx.x;
    int lane = tid & 31;
    int warp = tid >> 5;
    int warp_m = warp & 3;
    int warp_n = warp >> 2;
    int m0 = blockIdx.y * 128;
    int n0 = blockIdx.x * 128;

    int q = lane >> 3;
    int lrow = lane & 7;
    int arow_l = (q & 1) * 8 + lrow;
    int ksel = q >> 1;

    float acc[2][8][4];
#pragma unroll
    for (int i = 0; i < 2; i++)
#pragma unroll
        for (int j = 0; j < 8; j++)
#pragma unroll
            for (int k = 0; k < 4; k++) acc[i][j][k] = 0.f;

    auto load_chunk = [&](int c) {
        int k0 = c * 32;
        uint32_t buf = sb + (uint32_t)(c & 1) * 32768u;
#pragma unroll
        for (int t = 0; t < 8; t++) {
            int g = tid + t * 256;
            int mat = g >> 9;
            int inner = g & 511;
            int r = inner >> 2;
            int s = inner & 3;
            const __nv_bfloat16* base =
                (mat == 0) ? Ah : (mat == 1) ? Al : (mat == 2) ? Bh : Bl;
            int row = ((mat < 2) ? m0 : n0) + r;
            const void* src = base + (size_t)row * 2048 + k0 + s * 8;
            cp16(buf + (uint32_t)mat * 8192u + swz_off(r, s), src);
        }
        asm volatile("cp.async.commit_group;" ::: "memory");
    };

    load_chunk(0);

    for (int c = 0; c < 64; c++) {
        if (c + 1 < 64) load_chunk(c + 1);
        if (c + 1 < 64) asm volatile("cp.async.wait_group 1;" ::: "memory");
        else            asm volatile("cp.async.wait_group 0;" ::: "memory");
        __syncthreads();

        uint32_t buf = sb + (uint32_t)(c & 1) * 32768u;
        uint32_t bAh = buf, bAl = buf + 8192, bBh = buf + 16384, bBl = buf + 24576;

#pragma unroll
        for (int ks = 0; ks < 2; ks++) {
            int s = ks * 2 + ksel;
            uint32_t ah[2][4], al[2][4];
#pragma unroll
            for (int mi = 0; mi < 2; mi++) {
                int r = warp_m * 32 + mi * 16 + arow_l;
                ldm_x4(ah[mi], bAh + swz_off(r, s));
                ldm_x4(al[mi], bAl + swz_off(r, s));
            }
            uint32_t bh[8][2], bl[8][2];
#pragma unroll
            for (int j = 0; j < 4; j++) {
                int r = warp_n * 64 + j * 16 + arow_l;
                uint32_t t4[4];
                ldm_x4(t4, bBh + swz_off(r, s));
                bh[j * 2 + 0][0] = t4[0]; bh[j * 2 + 0][1] = t4[2];
                bh[j * 2 + 1][0] = t4[1]; bh[j * 2 + 1][1] = t4[3];
                ldm_x4(t4, bBl + swz_off(r, s));
                bl[j * 2 + 0][0] = t4[0]; bl[j * 2 + 0][1] = t4[2];
                bl[j * 2 + 1][0] = t4[1]; bl[j * 2 + 1][1] = t4[3];
            }
#pragma unroll
            for (int mi = 0; mi < 2; mi++) {
#pragma unroll
                for (int nj = 0; nj < 8; nj++) {
                    mma_bf16(acc[mi][nj], ah[mi], bh[nj][0], bh[nj][1]);
                    mma_bf16(acc[mi][nj], ah[mi], bl[nj][0], bl[nj][1]);
                    mma_bf16(acc[mi][nj], al[mi], bh[nj][0], bh[nj][1]);
                }
            }
        }
        __syncthreads();
    }

    int rr = lane >> 2;
    int cc = (lane & 3) * 2;
#pragma unroll
    for (int mi = 0; mi < 2; mi++) {
        int r1 = m0 + warp_m * 32 + mi * 16 + rr;
#pragma unroll
        for (int nj = 0; nj < 8; nj++) {
            int col = n0 + warp_n * 64 + nj * 8 + cc;
            float2 v0 = make_float2(acc[mi][nj][0], acc[mi][nj][1]);
            float2 v1 = make_float2(acc[mi][nj][2], acc[mi][nj][3]);
            *(float2*)&C[(size_t)r1 * ldc + col] = v0;
            *(float2*)&C[(size_t)(r1 + 8) * ldc + col] = v1;
        }
    }
}

// ---------------------------------------------------------------------------
// Elementwise fp32 -> (bf16 hi, bf16 lo) split
// ---------------------------------------------------------------------------
__global__ __launch_bounds__(256) void split_kernel(
    const float* __restrict__ src, __nv_bfloat16* __restrict__ hi,
    __nv_bfloat16* __restrict__ lo, int n4)
{
    int i = blockIdx.x * 256 + threadIdx.x;
    if (i >= n4) return;
    float4 v = ((const float4*)src)[i];
    __nv_bfloat16 h0 = __float2bfloat16(v.x);
    __nv_bfloat16 h1 = __float2bfloat16(v.y);
    __nv_bfloat16 h2 = __float2bfloat16(v.z);
    __nv_bfloat16 h3 = __float2bfloat16(v.w);
    __nv_bfloat16 l0 = __float2bfloat16(v.x - __bfloat162float(h0));
    __nv_bfloat16 l1 = __float2bfloat16(v.y - __bfloat162float(h1));
    __nv_bfloat16 l2 = __float2bfloat16(v.z - __bfloat162float(h2));
    __nv_bfloat16 l3 = __float2bfloat16(v.w - __bfloat162float(h3));
    ushort4 hv = make_ushort4(__bfloat16_as_ushort(h0), __bfloat16_as_ushort(h1),
                              __bfloat16_as_ushort(h2), __bfloat16_as_ushort(h3));
    ushort4 lv = make_ushort4(__bfloat16_as_ushort(l0), __bfloat16_as_ushort(l1),
                              __bfloat16_as_ushort(l2), __bfloat16_as_ushort(l3));
    ((ushort4*)hi)[i] = hv;
    ((ushort4*)lo)[i] = lv;
}

// ---------------------------------------------------------------------------
// Transpose + split W_O: in [he=2048][d=2048] -> out [d][he] hi/lo bf16
// ---------------------------------------------------------------------------
__global__ __launch_bounds__(256) void transpose_split_wo(
    const float* __restrict__ W, __nv_bfloat16* __restrict__ Th,
    __nv_bfloat16* __restrict__ Tl)
{
    __shared__ float t[32][33];
    int bx = blockIdx.x * 32;
    int by = blockIdx.y * 32;
    int x = threadIdx.x & 31;
    int y0 = threadIdx.x >> 5;
#pragma unroll
    for (int i = 0; i < 32; i += 8)
        t[y0 + i][x] = W[(size_t)(by + y0 + i) * 2048 + bx + x];
    __syncthreads();
#pragma unroll
    for (int i = 0; i < 32; i += 8) {
        float v = t[x][y0 + i];
        __nv_bfloat16 h = __float2bfloat16(v);
        __nv_bfloat16 l = __float2bfloat16(v - __bfloat162float(h));
        size_t o = (size_t)(bx + y0 + i) * 2048 + by + x;
        Th[o] = h;
        Tl[o] = l;
    }
}

// ---------------------------------------------------------------------------
// RoPE + precision-split producer:
//  q: rope, scale by 1/sqrt(Dh), split -> Qhi/Qlo (reusing g_Ahi/g_Alo)
//  k: rope -> fp32 k_cache + split -> Khi/Klo
//  v: copy -> fp32 v_cache + split -> Vhi/Vlo
// ---------------------------------------------------------------------------
__global__ __launch_bounds__(256) void rope_split_kernel(
    const float* __restrict__ qkv,
    float* __restrict__ kc, float* __restrict__ vc,
    __nv_bfloat16* __restrict__ Qhi, __nv_bfloat16* __restrict__ Qlo,
    __nv_bfloat16* __restrict__ Khi, __nv_bfloat16* __restrict__ Klo,
    __nv_bfloat16* __restrict__ Vhi, __nv_bfloat16* __restrict__ Vlo,
    const int* __restrict__ sp_ptr)
{
    const float LOG2_BASE_OVER_HALF = 13.287712379549449f / 64.0f;
    const float scale = 0.08838834764831845f;  // 1/sqrt(128)
    int m = blockIdx.x;
    int s = m & (S_ - 1);
    int sp = *sp_ptr;
    float pos = (float)(sp + s);
    int tid = threadIdx.x;

    // q: 16 heads x 64 pairs
    for (int p = tid; p < H_ * 64; p += 256) {
        int h = p >> 6, e = p & 63;
        float inv = exp2f(-(float)e * LOG2_BASE_OVER_HALF);
        float ang = pos * inv;
        float sn, cs;
        sincosf(ang, &sn, &cs);
        const float* base = qkv + (size_t)m * NQKV + h * DH_;
        float x1 = base[e], x2 = base[e + 64];
        float y1 = (x1 * cs - x2 * sn) * scale;
        float y2 = (x1 * sn + x2 * cs) * scale;
        size_t o = (size_t)m * D_ + h * DH_;
        __nv_bfloat16 h1 = __float2bfloat16(y1);
        __nv_bfloat16 h2 = __float2bfloat16(y2);
        Qhi[o + e]      = h1;
        Qhi[o + e + 64] = h2;
        Qlo[o + e]      = __float2bfloat16(y1 - __bfloat162float(h1));
        Qlo[o + e + 64] = __float2bfloat16(y2 - __bfloat162float(h2));
    }
    // k: 4 heads x 64 pairs
    for (int p = tid; p < KVH_ * 64; p += 256) {
        int h = p >> 6, e = p & 63;
        float inv = exp2f(-(float)e * LOG2_BASE_OVER_HALF);
        float ang = pos * inv;
        float sn, cs;
        sincosf(ang, &sn, &cs);
        const float* base = qkv + (size_t)m * NQKV + 2048 + h * DH_;
        float x1 = base[e], x2 = base[e + 64];
        float y1 = x1 * cs - x2 * sn;
        float y2 = x1 * sn + x2 * cs;
        size_t o = (size_t)m * (KVH_ * DH_) + h * DH_;
        kc[o + e]      = y1;
        kc[o + e + 64] = y2;
        __nv_bfloat16 h1 = __float2bfloat16(y1);
        __nv_bfloat16 h2 = __float2bfloat16(y2);
        Khi[o + e]      = h1;
        Khi[o + e + 64] = h2;
        Klo[o + e]      = __float2bfloat16(y1 - __bfloat162float(h1));
        Klo[o + e + 64] = __float2bfloat16(y2 - __bfloat162float(h2));
    }
    // v
    for (int i = tid; i < KVH_ * DH_; i += 256) {
        float v = qkv[(size_t)m * NQKV + 2560 + i];
        size_t o = (size_t)m * (KVH_ * DH_) + i;
        vc[o] = v;
        __nv_bfloat16 h = __float2bfloat16(v);
        Vhi[o] = h;
        Vlo[o] = __float2bfloat16(v - __bfloat162float(h));
    }
}

// ---------------------------------------------------------------------------
// Tensor-core flash attention, split-bf16 numerics.
// BM=64, BN=64, Dh=128. 4 warps, warp = m16 rows. 2 CTAs/SM.
// ---------------------------------------------------------------------------
#define ATT2_SMEM (6 * 16384)   // Qhi Qlo Khi Klo Vhi Vlo, each 64x128 bf16

__global__ __launch_bounds__(128, 2) void attn_mma_kernel(
    const __nv_bfloat16* __restrict__ Qhi, const __nv_bfloat16* __restrict__ Qlo,
    const __nv_bfloat16* __restrict__ Khi, const __nv_bfloat16* __restrict__ Klo,
    const __nv_bfloat16* __restrict__ Vhi, const __nv_bfloat16* __restrict__ Vlo,
    __nv_bfloat16* __restrict__ Ohi, __nv_bfloat16* __restrict__ Olo,
    const int* __restrict__ sp_ptr)
{
    extern __shared__ char smem[];
    uint32_t sb = smem_u32(smem);
    const uint32_t sQh = sb, sQl = sb + 16384;
    const uint32_t sKh = sb + 32768, sKl = sb + 49152;
    const uint32_t sVh = sb + 65536, sVl = sb + 81920;

    int tid = threadIdx.x;
    int lane = tid & 31;
    int warp = tid >> 5;
    int bh = blockIdx.y;
    int b = bh >> 4, h = bh & 15, kvh = h >> 2;
    int q0 = blockIdx.x * 64;
    int sp = *sp_ptr;
    float slope = exp2f(-0.5f * (float)(h + 1));

    // ldmatrix per-lane addressing: q = lane>>3
    int fr = ((lane >> 3) & 1) * 8 + (lane & 7);   // row offset within 16
    int fs = lane >> 4;                             // seg offset 0/1

    // ---- load Q tile (64x128) hi/lo via cp.async ----
#pragma unroll
    for (int i = 0; i < 16; i++) {
        int idx = tid + i * 128;          // 0..2047
        int t = idx >> 10;                // 0 hi, 1 lo
        int inner = idx & 1023;
        int r = inner >> 4, sg = inner & 15;
        const __nv_bfloat16* src = (t ? Qlo : Qhi)
            + (size_t)(b * S_ + q0 + r) * 2048 + h * 128 + sg * 8;
        cp16((t ? sQl : sQh) + aswz(r, sg), src);
    }
    asm volatile("cp.async.commit_group;" ::: "memory");

    float Oacc[16][4];
#pragma unroll
    for (int e = 0; e < 16; e++)
#pragma unroll
        for (int k = 0; k < 4; k++) Oacc[e][k] = 0.f;
    float m0r = -1e30f, m1r = -1e30f;
    float l0r = 0.f, l1r = 0.f;

    int kt_end = (sp + q0 + 63) >> 6;
    if (kt_end > S_ / 64 - 1) kt_end = S_ / 64 - 1;

    asm volatile("cp.async.wait_group 0;" ::: "memory");
    __syncthreads();

    int row0 = q0 + warp * 16 + (lane >> 2);
    int qp0 = sp + row0, qp1 = qp0 + 8;

    for (int kt = 0; kt <= kt_end; kt++) {
        int k0 = kt * 64;
        // ---- load K/V tiles ----
#pragma unroll
        for (int i = 0; i < 32; i++) {
            int idx = tid + i * 128;   // 0..4095
            int t = idx >> 10;         // 0 Khi 1 Klo 2 Vhi 3 Vlo
            int inner = idx & 1023;
            int r = inner >> 4, sg = inner & 15;
            const __nv_bfloat16* basep =
                (t == 0) ? Khi : (t == 1) ? Klo : (t == 2) ? Vhi : Vlo;
            const __nv_bfloat16* src =
                basep + (size_t)(b * S_ + k0 + r) * 512 + kvh * 128 + sg * 8;
            uint32_t dstb = (t == 0) ? sKh : (t == 1) ? sKl : (t == 2) ? sVh : sVl;
            cp16(dstb + aswz(r, sg), src);
        }
        asm volatile("cp.async.commit_group;" ::: "memory");
        asm volatile("cp.async.wait_group 0;" ::: "memory");
        __syncthreads();

        // ---- S = Q K^T (split: hh + hl + lh) ----
        float sacc[8][4];
#pragma unroll
        for (int nj = 0; nj < 8; nj++)
#pragma unroll
            for (int k = 0; k < 4; k++) sacc[nj][k] = 0.f;

#pragma unroll
        for (int s = 0; s < 8; s++) {
            uint32_t qh[4], ql[4], t4[4];
            ldm_x4(qh, sQh + aswz(warp * 16 + fr, 2 * s + fs));
            ldm_x4(ql, sQl + aswz(warp * 16 + fr, 2 * s + fs));
            uint32_t kbh[8][2], kbl[8][2];
#pragma unroll
            for (int j = 0; j < 4; j++) {
                ldm_x4(t4, sKh + aswz(j * 16 + fr, 2 * s + fs));
                kbh[2 * j][0] = t4[0]; kbh[2 * j][1] = t4[2];
                kbh[2 * j + 1][0] = t4[1]; kbh[2 * j + 1][1] = t4[3];
                ldm_x4(t4, sKl + aswz(j * 16 + fr, 2 * s + fs));
                kbl[2 * j][0] = t4[0]; kbl[2 * j][1] = t4[2];
                kbl[2 * j + 1][0] = t4[1]; kbl[2 * j + 1][1] = t4[3];
            }
#pragma unroll
            for (int nj = 0; nj < 8; nj++) {
                mma_bf16(sacc[nj], qh, kbh[nj][0], kbh[nj][1]);
                mma_bf16(sacc[nj], qh, kbl[nj][0], kbl[nj][1]);
                mma_bf16(sacc[nj], ql, kbh[nj][0], kbh[nj][1]);
            }
        }

        // ---- bias + causal mask ----
#pragma unroll
        for (int nj = 0; nj < 8; nj++) {
            int c = k0 + nj * 8 + (lane & 3) * 2;
            sacc[nj][0] = (c     <= qp0) ? sacc[nj][0] - slope * (float)(qp0 - c)     : -1e30f;
            sacc[nj][1] = (c + 1 <= qp0) ? sacc[nj][1] - slope * (float)(qp0 - c - 1) : -1e30f;
            sacc[nj][2] = (c     <= qp1) ? sacc[nj][2] - slope * (float)(qp1 - c)     : -1e30f;
            sacc[nj][3] = (c + 1 <= qp1) ? sacc[nj][3] - slope * (float)(qp1 - c - 1) : -1e30f;
        }

        // ---- online softmax (row stats in quad) ----
        float mx0 = -1e30f, mx1 = -1e30f;
#pragma unroll
        for (int nj = 0; nj < 8; nj++) {
            mx0 = fmaxf(mx0, fmaxf(sacc[nj][0], sacc[nj][1]));
            mx1 = fmaxf(mx1, fmaxf(sacc[nj][2], sacc[nj][3]));
        }
        mx0 = fmaxf(mx0, __shfl_xor_sync(0xffffffffu, mx0, 1));
        mx0 = fmaxf(mx0, __shfl_xor_sync(0xffffffffu, mx0, 2));
        mx1 = fmaxf(mx1, __shfl_xor_sync(0xffffffffu, mx1, 1));
        mx1 = fmaxf(mx1, __shfl_xor_sync(0xffffffffu, mx1, 2));
        float mn0 = fmaxf(m0r, mx0), mn1 = fmaxf(m1r, mx1);
        float corr0 = __expf(m0r - mn0), corr1 = __expf(m1r - mn1);
        m0r = mn0; m1r = mn1;

        float ls0 = 0.f, ls1 = 0.f;
#pragma unroll
        for (int nj = 0; nj < 8; nj++) {
            sacc[nj][0] = __expf(sacc[nj][0] - mn0);
            sacc[nj][1] = __expf(sacc[nj][1] - mn0);
            sacc[nj][2] = __expf(sacc[nj][2] - mn1);
            sacc[nj][3] = __expf(sacc[nj][3] - mn1);
            ls0 += sacc[nj][0] + sacc[nj][1];
            ls1 += sacc[nj][2] + sacc[nj][3];
        }
        ls0 += __shfl_xor_sync(0xffffffffu, ls0, 1);
        ls0 += __shfl_xor_sync(0xffffffffu, ls0, 2);
        ls1 += __shfl_xor_sync(0xffffffffu, ls1, 1);
        ls1 += __shfl_xor_sync(0xffffffffu, ls1, 2);
        l0r = l0r * corr0 + ls0;
        l1r = l1r * corr1 + ls1;

        // rescale O
#pragma unroll
        for (int e = 0; e < 16; e++) {
            Oacc[e][0] *= corr0; Oacc[e][1] *= corr0;
            Oacc[e][2] *= corr1; Oacc[e][3] *= corr1;
        }

        // ---- P -> bf16 hi/lo A-fragments ----
        uint32_t phi[4][4], plo[4][4];
#pragma unroll
        for (int t = 0; t < 4; t++) {
            float r0, r1;
            phi[t][0] = pack_hi2(sacc[2 * t][0], sacc[2 * t][1], r0, r1);
            plo[t][0] = pack_bf2(r0, r1);
            phi[t][1] = pack_hi2(sacc[2 * t][2], sacc[2 * t][3], r0, r1);
            plo[t][1] = pack_bf2(r0, r1);
            phi[t][2] = pack_hi2(sacc[2 * t + 1][0], sacc[2 * t + 1][1], r0, r1);
            plo[t][2] = pack_bf2(r0, r1);
            phi[t][3] = pack_hi2(sacc[2 * t + 1][2], sacc[2 * t + 1][3], r0, r1);
            plo[t][3] = pack_bf2(r0, r1);
        }

        // ---- O += P V (split: hh + hl + lh) ----
#pragma unroll
        for (int t = 0; t < 4; t++) {
#pragma unroll
            for (int u = 0; u < 8; u++) {
                uint32_t th[4], tl[4];
                ldm_x4_t(th, sVh + aswz(t * 16 + fr, 2 * u + fs));
                ldm_x4_t(tl, sVl + aswz(t * 16 + fr, 2 * u + fs));
                mma_bf16(Oacc[2 * u], phi[t], th[0], th[1]);
                mma_bf16(Oacc[2 * u], phi[t], tl[0], tl[1]);
                mma_bf16(Oacc[2 * u], plo[t], th[0], th[1]);
                mma_bf16(Oacc[2 * u + 1], phi[t], th[2], th[3]);
                mma_bf16(Oacc[2 * u + 1], phi[t], tl[2], tl[3]);
                mma_bf16(Oacc[2 * u + 1], plo[t], th[2], th[3]);
            }
        }
        __syncthreads();   // protect smem before next iteration's loads
    }

    // ---- epilogue: normalize + split to bf16 hi/lo ----
    float inv0 = 1.f / l0r, inv1 = 1.f / l1r;
    size_t row0g = (size_t)(b * S_ + row0);
#pragma unroll
    for (int e = 0; e < 16; e++) {
        int colb = h * 128 + e * 8 + (lane & 3) * 2;
        float x0 = Oacc[e][0] * inv0, x1 = Oacc[e][1] * inv0;
        float x2 = Oacc[e][2] * inv1, x3 = Oacc[e][3] * inv1;
        float r0, r1;
        uint32_t hp0 = pack_hi2(x0, x1, r0, r1);
        uint32_t lp0 = pack_bf2(r0, r1);
        uint32_t hp1 = pack_hi2(x2, x3, r0, r1);
        uint32_t lp1 = pack_bf2(r0, r1);
        *(uint32_t*)&Ohi[row0g * 2048 + colb] = hp0;
        *(uint32_t*)&Olo[row0g * 2048 + colb] = lp0;
        *(uint32_t*)&Ohi[(row0g + 8) * 2048 + colb] = hp1;
        *(uint32_t*)&Olo[(row0g + 8) * 2048 + colb] = lp1;
    }
}

// ---------------------------------------------------------------------------
extern "C" void kernel_launch(void* const* d_in, const int* in_sizes, int n_in,
                              void* d_out, int out_size)
{
    const float* residual = (const float*)d_in[0];
    const float* W_Q = (const float*)d_in[1];
    const float* W_K = (const float*)d_in[2];
    const float* W_V = (const float*)d_in[3];
    const float* W_O = (const float*)d_in[4];
    const int* sp = (const int*)d_in[5];

    float* out = (float*)d_out;
    float* k_cache = out + (size_t)B_ * S_ * D_;
    float* v_cache = k_cache + (size_t)B_ * S_ * KVH_ * DH_;

    float* qkv_ptr;
    __nv_bfloat16 *Ahi, *Alo, *Whi, *Wlo, *WOhi, *WOlo, *Phi, *Plo;
    __nv_bfloat16 *Khi, *Klo, *Vhi, *Vlo;
    cudaGetSymbolAddress((void**)&qkv_ptr, g_qkv);
    cudaGetSymbolAddress((void**)&Ahi, g_Ahi);
    cudaGetSymbolAddress((void**)&Alo, g_Alo);
    cudaGetSymbolAddress((void**)&Whi, g_Whi);
    cudaGetSymbolAddress((void**)&Wlo, g_Wlo);
    cudaGetSymbolAddress((void**)&WOhi, g_WOhi);
    cudaGetSymbolAddress((void**)&WOlo, g_WOlo);
    cudaGetSymbolAddress((void**)&Phi, g_Phi);
    cudaGetSymbolAddress((void**)&Plo, g_Plo);
    cudaGetSymbolAddress((void**)&Khi, g_Khi);
    cudaGetSymbolAddress((void**)&Klo, g_Klo);
    cudaGetSymbolAddress((void**)&Vhi, g_Vhi);
    cudaGetSymbolAddress((void**)&Vlo, g_Vlo);

    cudaFuncSetAttribute(hmma_gemm, cudaFuncAttributeMaxDynamicSharedMemorySize,
                         GEMM_SMEM);
    cudaFuncSetAttribute(attn_mma_kernel, cudaFuncAttributeMaxDynamicSharedMemorySize,
                         ATT2_SMEM);

    // 0) splits
    split_kernel<<<(M_ * D_ / 4 + 255) / 256, 256>>>(residual, Ahi, Alo, M_ * D_ / 4);
    split_kernel<<<(2048 * 2048 / 4 + 255) / 256, 256>>>(W_Q, Whi, Wlo, 2048 * 2048 / 4);
    split_kernel<<<(512 * 2048 / 4 + 255) / 256, 256>>>(
        W_K, Whi + (size_t)2048 * 2048, Wlo + (size_t)2048 * 2048, 512 * 2048 / 4);
    split_kernel<<<(512 * 2048 / 4 + 255) / 256, 256>>>(
        W_V, Whi + (size_t)2560 * 2048, Wlo + (size_t)2560 * 2048, 512 * 2048 / 4);
    transpose_split_wo<<<dim3(64, 64), 256>>>(W_O, WOhi, WOlo);

    // 1) fused QKV projection (HMMA split-bf16)
    hmma_gemm<<<dim3(NQKV / 128, M_ / 128), 256, GEMM_SMEM>>>(
        Ahi, Alo, Whi, Wlo, qkv_ptr, NQKV);

    // 2) RoPE + split producer (reuses Ahi/Alo as Qhi/Qlo)
    rope_split_kernel<<<M_, 256>>>(qkv_ptr, k_cache, v_cache,
                                   Ahi, Alo, Khi, Klo, Vhi, Vlo, sp);

    // 3) tensor-core attention -> bf16 hi/lo output (Phi/Plo)
    attn_mma_kernel<<<dim3(S_ / 64, B_ * H_), 128, ATT2_SMEM>>>(
        Ahi, Alo, Khi, Klo, Vhi, Vlo, Phi, Plo, sp);

    // 4) output projection (HMMA split-bf16)
    hmma_gemm<<<dim3(D_ / 128, M_ / 128), 256, GEMM_SMEM>>>(
        Phi, Plo, WOhi, WOlo, out, D_);
}